// round 3
// baseline (speedup 1.0000x reference)
#include <cuda_runtime.h>

#define TH 16
#define TW 64
#define NT 384
#define HIMG 512
#define WIMG 512
#define SAW 68   // padded row stride for s_a
#define SCW 36   // padded row stride for s_c (half-res chroma)

__global__ __launch_bounds__(NT, 4) void jpeg_kernel(
    const float* __restrict__ in, const float* __restrict__ quant,
    const float* __restrict__ dct, float* __restrict__ out)
{
    __shared__ float s_a[3][TH][SAW];  // y full-res; later V scratch; later recon
    __shared__ float s_c[2][TH/2][SCW];// half-res chroma (cb, cr), mean-128
    __shared__ float s_d[8][9];        // D
    __shared__ float s_dt[8][9];       // D^T
    __shared__ float s_e[8][4];        // E = D*U (8x4), chroma DCT operator
    __shared__ float s_q[3][8][9];     // quant table

    const int tid = threadIdx.x;
    const int b   = blockIdx.z;
    const int ty0 = blockIdx.y * TH;
    const int tx0 = blockIdx.x * TW;

    // ---- tables ----
    if (tid < 64) {
        float v = dct[tid];
        int i = tid >> 3, j = tid & 7;
        s_d[i][j]  = v;
        s_dt[j][i] = v;
    } else if (tid < 256) {
        int i = tid - 64;
        float qv = rintf(quant[i] * 255.0f);
        float q1 = rintf((qv * 50.0f + 50.0f) / 100.0f);
        s_q[i >> 6][(i >> 3) & 7][i & 7] = fminf(fmaxf(q1, 1.0f), 255.0f);
    } else if (tid < 288) {
        int t = tid - 256;
        int i = t >> 2, h = t & 3;
        s_e[i][h] = dct[i * 8 + 2 * h] + dct[i * 8 + 2 * h + 1];
    }

    const size_t plane = (size_t)HIMG * WIMG;
    const float* base  = in  + (size_t)b * 3 * plane;
    float*       obase = out + (size_t)b * 3 * plane;

    // ---- phase 1: RGB->YCbCr + clip; y full-res, chroma 2x2-mean half-res ----
    if (tid < (TH/2) * (TW/2)) {                 // 256 quads
        const int qy = tid >> 5;                 // 0..7
        const int qx = tid & 31;                 // 0..31
        const int py = qy * 2, px = qx * 2;
        const size_t idx = (size_t)(ty0 + py) * WIMG + (tx0 + px);

        float2 r0 = *(const float2*)&base[idx];
        float2 r1 = *(const float2*)&base[idx + WIMG];
        float2 g0 = *(const float2*)&base[plane + idx];
        float2 g1 = *(const float2*)&base[plane + idx + WIMG];
        float2 b0 = *(const float2*)&base[2*plane + idx];
        float2 b1 = *(const float2*)&base[2*plane + idx + WIMG];

        float r00 = 255.0f*r0.x, r01 = 255.0f*r0.y, r10 = 255.0f*r1.x, r11 = 255.0f*r1.y;
        float g00 = 255.0f*g0.x, g01 = 255.0f*g0.y, g10 = 255.0f*g1.x, g11 = 255.0f*g1.y;
        float b00 = 255.0f*b0.x, b01 = 255.0f*b0.y, b10 = 255.0f*b1.x, b11 = 255.0f*b1.y;

        #define YV(R,G,B)  fmaf(0.114f,(B), fmaf(0.587f,(G), 0.299f*(R)))
        #define CBV(R,G,B) (fmaf(0.5f,(B),  fmaf(-0.331264108f,(G), -0.168735892f*(R))) + 128.0f)
        #define CRV(R,G,B) (fmaf(-0.081312411f,(B), fmaf(-0.418687589f,(G), 0.5f*(R))) + 128.0f)
        #define CL(v) fminf(fmaxf((v), 0.0f), 255.0f)

        float y00 = CL(YV(r00,g00,b00)) - 128.0f;
        float y01 = CL(YV(r01,g01,b01)) - 128.0f;
        float y10 = CL(YV(r10,g10,b10)) - 128.0f;
        float y11 = CL(YV(r11,g11,b11)) - 128.0f;

        float cb00 = CL(CBV(r00,g00,b00)), cb01 = CL(CBV(r01,g01,b01));
        float cb10 = CL(CBV(r10,g10,b10)), cb11 = CL(CBV(r11,g11,b11));
        float cr00 = CL(CRV(r00,g00,b00)), cr01 = CL(CRV(r01,g01,b01));
        float cr10 = CL(CRV(r10,g10,b10)), cr11 = CL(CRV(r11,g11,b11));

        float cbm = 0.25f * (((cb00 + cb01) + cb10) + cb11) - 128.0f;
        float crm = 0.25f * (((cr00 + cr01) + cr10) + cr11) - 128.0f;

        *(float2*)&s_a[0][py][px]   = make_float2(y00, y01);
        *(float2*)&s_a[0][py+1][px] = make_float2(y10, y11);
        s_c[0][qy][qx] = cbm;
        s_c[1][qy][qx] = crm;
    }
    __syncthreads();

    // ---- assignment: 48 (channel, block) units * 8 row-threads ----
    const int blk = tid >> 3;     // 0..47
    const int r   = tid & 7;
    int c, by, bx;
    if (blk < 16) { c = 0; by = blk >> 3; bx = blk & 7; }
    else { int t = blk - 16; c = 1 + (t >> 4); int rem = t & 15; by = rem >> 3; bx = rem & 7; }

    // ---- DCT -> quantize -> dequantize -> V = dec*D  (all row-local) ----
    float V[8];
    {
        float acc[8];
        if (c == 0) {
            // tmp = row r of D*X
            float tmp[8];
            #pragma unroll
            for (int k = 0; k < 8; k++) tmp[k] = 0.0f;
            #pragma unroll
            for (int j = 0; j < 8; j++) {
                float d = s_d[r][j];
                const float4 x0 = *(const float4*)&s_a[0][by*8 + j][bx*8];
                const float4 x1 = *(const float4*)&s_a[0][by*8 + j][bx*8 + 4];
                tmp[0] = fmaf(d, x0.x, tmp[0]);  tmp[1] = fmaf(d, x0.y, tmp[1]);
                tmp[2] = fmaf(d, x0.z, tmp[2]);  tmp[3] = fmaf(d, x0.w, tmp[3]);
                tmp[4] = fmaf(d, x1.x, tmp[4]);  tmp[5] = fmaf(d, x1.y, tmp[5]);
                tmp[6] = fmaf(d, x1.z, tmp[6]);  tmp[7] = fmaf(d, x1.w, tmp[7]);
            }
            // acc = tmp * D^T  (read D^T rows as float4)
            #pragma unroll
            for (int l = 0; l < 8; l++) acc[l] = 0.0f;
            #pragma unroll
            for (int k = 0; k < 8; k++) {
                float t = tmp[k];
                const float4 d0 = *(const float4*)&s_dt[k][0];
                const float4 d1 = *(const float4*)&s_dt[k][4];
                acc[0] = fmaf(t, d0.x, acc[0]);  acc[1] = fmaf(t, d0.y, acc[1]);
                acc[2] = fmaf(t, d0.z, acc[2]);  acc[3] = fmaf(t, d0.w, acc[3]);
                acc[4] = fmaf(t, d1.x, acc[4]);  acc[5] = fmaf(t, d1.y, acc[5]);
                acc[6] = fmaf(t, d1.z, acc[6]);  acc[7] = fmaf(t, d1.w, acc[7]);
            }
        } else {
            // chroma: Y = E * X_half * E^T   (E is 8x4)
            const int cc = c - 1;
            float P0 = 0.0f, P1 = 0.0f, P2 = 0.0f, P3 = 0.0f;
            #pragma unroll
            for (int jh = 0; jh < 4; jh++) {
                float e = s_e[r][jh];
                const float4 xh = *(const float4*)&s_c[cc][by*4 + jh][bx*4];
                P0 = fmaf(e, xh.x, P0);  P1 = fmaf(e, xh.y, P1);
                P2 = fmaf(e, xh.z, P2);  P3 = fmaf(e, xh.w, P3);
            }
            #pragma unroll
            for (int l = 0; l < 8; l++) {
                const float4 el = *(const float4*)&s_e[l][0];
                acc[l] = fmaf(P3, el.w, fmaf(P2, el.z, fmaf(P1, el.y, P0 * el.x)));
            }
        }
        // quantize / dequantize
        float dec[8];
        #pragma unroll
        for (int l = 0; l < 8; l++) {
            float q = s_q[c][r][l];
            dec[l]  = rintf(rintf(acc[l] / q) * q);
        }
        // V = dec * D  (row-local first IDCT stage)
        #pragma unroll
        for (int l = 0; l < 8; l++) V[l] = 0.0f;
        #pragma unroll
        for (int k = 0; k < 8; k++) {
            float t = dec[k];
            const float4 d0 = *(const float4*)&s_d[k][0];
            const float4 d1 = *(const float4*)&s_d[k][4];
            V[0] = fmaf(t, d0.x, V[0]);  V[1] = fmaf(t, d0.y, V[1]);
            V[2] = fmaf(t, d0.z, V[2]);  V[3] = fmaf(t, d0.w, V[3]);
            V[4] = fmaf(t, d1.x, V[4]);  V[5] = fmaf(t, d1.y, V[5]);
            V[6] = fmaf(t, d1.z, V[6]);  V[7] = fmaf(t, d1.w, V[7]);
        }
    }
    __syncthreads();  // all X reads done -> safe to overwrite s_a
    *(float4*)&s_a[c][by*8 + r][bx*8]     = make_float4(V[0], V[1], V[2], V[3]);
    *(float4*)&s_a[c][by*8 + r][bx*8 + 4] = make_float4(V[4], V[5], V[6], V[7]);
    __syncthreads();

    // ---- IDCT stage 2: Z = D^T * V ----
    float zr[8];
    {
        #pragma unroll
        for (int l = 0; l < 8; l++) zr[l] = 0.0f;
        #pragma unroll
        for (int j = 0; j < 8; j++) {
            float d = s_dt[r][j];  // = D[j][r]
            const float4 v0 = *(const float4*)&s_a[c][by*8 + j][bx*8];
            const float4 v1 = *(const float4*)&s_a[c][by*8 + j][bx*8 + 4];
            zr[0] = fmaf(d, v0.x, zr[0]);  zr[1] = fmaf(d, v0.y, zr[1]);
            zr[2] = fmaf(d, v0.z, zr[2]);  zr[3] = fmaf(d, v0.w, zr[3]);
            zr[4] = fmaf(d, v1.x, zr[4]);  zr[5] = fmaf(d, v1.y, zr[5]);
            zr[6] = fmaf(d, v1.z, zr[6]);  zr[7] = fmaf(d, v1.w, zr[7]);
        }
        const float off = (c == 0) ? 128.0f : 0.0f;
        #pragma unroll
        for (int l = 0; l < 8; l++) zr[l] += off;
    }
    __syncthreads();  // all V reads done -> safe to overwrite
    *(float4*)&s_a[c][by*8 + r][bx*8]     = make_float4(zr[0], zr[1], zr[2], zr[3]);
    *(float4*)&s_a[c][by*8 + r][bx*8 + 4] = make_float4(zr[4], zr[5], zr[6], zr[7]);
    __syncthreads();

    // ---- phase 5: YCbCr -> RGB, clip, round, store ----
    if (tid < (TH * TW) / 4) {
        const int py  = tid >> 4;
        const int px4 = (tid & 15) * 4;
        const float4 yv  = *(const float4*)&s_a[0][py][px4];
        const float4 cbv = *(const float4*)&s_a[1][py][px4];
        const float4 crv = *(const float4*)&s_a[2][py][px4];

        #define FIN(v) (rintf(fminf(fmaxf((v), 0.0f), 255.0f)) * (1.0f/255.0f))
        float4 R, G, Bv;
        R.x = FIN(fmaf(1.402f, crv.x, yv.x));  R.y = FIN(fmaf(1.402f, crv.y, yv.y));
        R.z = FIN(fmaf(1.402f, crv.z, yv.z));  R.w = FIN(fmaf(1.402f, crv.w, yv.w));
        G.x = FIN(fmaf(-0.714136286f, crv.x, fmaf(-0.344136286f, cbv.x, yv.x)));
        G.y = FIN(fmaf(-0.714136286f, crv.y, fmaf(-0.344136286f, cbv.y, yv.y)));
        G.z = FIN(fmaf(-0.714136286f, crv.z, fmaf(-0.344136286f, cbv.z, yv.z)));
        G.w = FIN(fmaf(-0.714136286f, crv.w, fmaf(-0.344136286f, cbv.w, yv.w)));
        Bv.x = FIN(fmaf(1.772f, cbv.x, yv.x)); Bv.y = FIN(fmaf(1.772f, cbv.y, yv.y));
        Bv.z = FIN(fmaf(1.772f, cbv.z, yv.z)); Bv.w = FIN(fmaf(1.772f, cbv.w, yv.w));

        const size_t idx = (size_t)(ty0 + py) * WIMG + (tx0 + px4);
        *(float4*)&obase[idx]           = R;
        *(float4*)&obase[plane + idx]   = G;
        *(float4*)&obase[2*plane + idx] = Bv;
    }
}

extern "C" void kernel_launch(void* const* d_in, const int* in_sizes, int n_in,
                              void* d_out, int out_size)
{
    const float* x = nullptr;
    const float* q = nullptr;
    const float* d = nullptr;
    int nimg = 0;
    for (int i = 0; i < n_in; i++) {
        if (in_sizes[i] == 192)      q = (const float*)d_in[i];
        else if (in_sizes[i] == 64)  d = (const float*)d_in[i];
        else { x = (const float*)d_in[i]; nimg = in_sizes[i] / (3 * HIMG * WIMG); }
    }
    dim3 grid(WIMG / TW, HIMG / TH, nimg);
    jpeg_kernel<<<grid, NT>>>(x, q, d, (float*)d_out);
}

// round 4
// speedup vs baseline: 1.2082x; 1.2082x over previous
#include <cuda_runtime.h>

#define TH 16
#define TW 64
#define NT 384
#define HIMG 512
#define WIMG 512
#define SAW 68   // padded row stride for s_a
#define SCW 36   // padded row stride for s_c (half-res chroma)

__global__ __launch_bounds__(NT, 4) void jpeg_kernel(
    const float* __restrict__ in, const float* __restrict__ quant,
    const float* __restrict__ dct, float* __restrict__ out)
{
    __shared__ float s_a[3][TH][SAW];   // y full-res; later V scratch; later recon
    __shared__ float s_c[2][TH/2][SCW]; // half-res chroma (cb, cr), mean-128
    __shared__ float s_d[8][9];         // D
    __shared__ float s_dt[8][9];        // D^T
    __shared__ float s_e[8][4];         // E = D*U (8x4), chroma DCT operator
    __shared__ float s_q[3][8][8];      // quant table (dense, vec4-loadable)
    __shared__ float s_rq[3][8][8];     // 1/q

    const int tid = threadIdx.x;
    const int b   = blockIdx.z;
    const int ty0 = blockIdx.y * TH;
    const int tx0 = blockIdx.x * TW;

    // ---- tables ----
    if (tid < 64) {
        float v = dct[tid];
        int i = tid >> 3, j = tid & 7;
        s_d[i][j]  = v;
        s_dt[j][i] = v;
    } else if (tid < 256) {
        int i = tid - 64;
        float qv = rintf(quant[i] * 255.0f);
        float q1 = rintf((qv * 50.0f + 50.0f) / 100.0f);
        float q  = fminf(fmaxf(q1, 1.0f), 255.0f);
        int ci = i >> 6, ri = (i >> 3) & 7, li = i & 7;
        s_q[ci][ri][li]  = q;
        s_rq[ci][ri][li] = 1.0f / q;
    } else if (tid < 288) {
        int t = tid - 256;
        int i = t >> 2, h = t & 3;
        s_e[i][h] = dct[i * 8 + 2 * h] + dct[i * 8 + 2 * h + 1];
    }

    const size_t plane = (size_t)HIMG * WIMG;
    const float* base  = in  + (size_t)b * 3 * plane;
    float*       obase = out + (size_t)b * 3 * plane;

    // ---- phase 1: RGB->YCbCr + clip; y full-res, chroma 2x2-mean half-res ----
    if (tid < (TH/2) * (TW/2)) {                 // 256 quads
        const int qy = tid >> 5;                 // 0..7
        const int qx = tid & 31;                 // 0..31
        const int py = qy * 2, px = qx * 2;
        const size_t idx = (size_t)(ty0 + py) * WIMG + (tx0 + px);

        float2 r0 = *(const float2*)&base[idx];
        float2 r1 = *(const float2*)&base[idx + WIMG];
        float2 g0 = *(const float2*)&base[plane + idx];
        float2 g1 = *(const float2*)&base[plane + idx + WIMG];
        float2 b0 = *(const float2*)&base[2*plane + idx];
        float2 b1 = *(const float2*)&base[2*plane + idx + WIMG];

        float r00 = 255.0f*r0.x, r01 = 255.0f*r0.y, r10 = 255.0f*r1.x, r11 = 255.0f*r1.y;
        float g00 = 255.0f*g0.x, g01 = 255.0f*g0.y, g10 = 255.0f*g1.x, g11 = 255.0f*g1.y;
        float b00 = 255.0f*b0.x, b01 = 255.0f*b0.y, b10 = 255.0f*b1.x, b11 = 255.0f*b1.y;

        #define YV(R,G,B)  fmaf(0.114f,(B), fmaf(0.587f,(G), 0.299f*(R)))
        #define CBV(R,G,B) (fmaf(0.5f,(B),  fmaf(-0.331264108f,(G), -0.168735892f*(R))) + 128.0f)
        #define CRV(R,G,B) (fmaf(-0.081312411f,(B), fmaf(-0.418687589f,(G), 0.5f*(R))) + 128.0f)
        #define CL(v) fminf(fmaxf((v), 0.0f), 255.0f)

        float y00 = CL(YV(r00,g00,b00)) - 128.0f;
        float y01 = CL(YV(r01,g01,b01)) - 128.0f;
        float y10 = CL(YV(r10,g10,b10)) - 128.0f;
        float y11 = CL(YV(r11,g11,b11)) - 128.0f;

        float cb00 = CL(CBV(r00,g00,b00)), cb01 = CL(CBV(r01,g01,b01));
        float cb10 = CL(CBV(r10,g10,b10)), cb11 = CL(CBV(r11,g11,b11));
        float cr00 = CL(CRV(r00,g00,b00)), cr01 = CL(CRV(r01,g01,b01));
        float cr10 = CL(CRV(r10,g10,b10)), cr11 = CL(CRV(r11,g11,b11));

        float cbm = 0.25f * (((cb00 + cb01) + cb10) + cb11) - 128.0f;
        float crm = 0.25f * (((cr00 + cr01) + cr10) + cr11) - 128.0f;

        *(float2*)&s_a[0][py][px]   = make_float2(y00, y01);
        *(float2*)&s_a[0][py+1][px] = make_float2(y10, y11);
        s_c[0][qy][qx] = cbm;
        s_c[1][qy][qx] = crm;
    }
    __syncthreads();

    // ---- assignment: 48 (channel, block) units * 8 row-threads ----
    const int blk = tid >> 3;     // 0..47
    const int r   = tid & 7;
    int c, by, bx;
    if (blk < 16) { c = 0; by = blk >> 3; bx = blk & 7; }
    else { int t = blk - 16; c = 1 + (t >> 4); int rem = t & 15; by = rem >> 3; bx = rem & 7; }

    // ---- DCT -> quantize -> dequantize -> V = dec*D  (all row-local) ----
    float V[8];
    {
        float acc[8];
        if (c == 0) {
            float tmp[8];
            #pragma unroll
            for (int k = 0; k < 8; k++) tmp[k] = 0.0f;
            const float* pX = &s_a[0][by*8][bx*8];
            #pragma unroll
            for (int j = 0; j < 8; j++) {
                float d = s_d[r][j];
                const float4 x0 = *(const float4*)(pX + j*SAW);
                const float4 x1 = *(const float4*)(pX + j*SAW + 4);
                tmp[0] = fmaf(d, x0.x, tmp[0]);  tmp[1] = fmaf(d, x0.y, tmp[1]);
                tmp[2] = fmaf(d, x0.z, tmp[2]);  tmp[3] = fmaf(d, x0.w, tmp[3]);
                tmp[4] = fmaf(d, x1.x, tmp[4]);  tmp[5] = fmaf(d, x1.y, tmp[5]);
                tmp[6] = fmaf(d, x1.z, tmp[6]);  tmp[7] = fmaf(d, x1.w, tmp[7]);
            }
            #pragma unroll
            for (int l = 0; l < 8; l++) acc[l] = 0.0f;
            #pragma unroll
            for (int k = 0; k < 8; k++) {
                float t = tmp[k];
                const float4 d0 = *(const float4*)&s_dt[k][0];
                const float4 d1 = *(const float4*)&s_dt[k][4];
                acc[0] = fmaf(t, d0.x, acc[0]);  acc[1] = fmaf(t, d0.y, acc[1]);
                acc[2] = fmaf(t, d0.z, acc[2]);  acc[3] = fmaf(t, d0.w, acc[3]);
                acc[4] = fmaf(t, d1.x, acc[4]);  acc[5] = fmaf(t, d1.y, acc[5]);
                acc[6] = fmaf(t, d1.z, acc[6]);  acc[7] = fmaf(t, d1.w, acc[7]);
            }
        } else {
            const int cc = c - 1;
            float P0 = 0.0f, P1 = 0.0f, P2 = 0.0f, P3 = 0.0f;
            const float* pC = &s_c[cc][by*4][bx*4];
            #pragma unroll
            for (int jh = 0; jh < 4; jh++) {
                float e = s_e[r][jh];
                const float4 xh = *(const float4*)(pC + jh*SCW);
                P0 = fmaf(e, xh.x, P0);  P1 = fmaf(e, xh.y, P1);
                P2 = fmaf(e, xh.z, P2);  P3 = fmaf(e, xh.w, P3);
            }
            #pragma unroll
            for (int l = 0; l < 8; l++) {
                const float4 el = *(const float4*)&s_e[l][0];
                acc[l] = fmaf(P3, el.w, fmaf(P2, el.z, fmaf(P1, el.y, P0 * el.x)));
            }
        }
        // quantize / dequantize (reciprocal, no FDIV)
        const float4 q0  = *(const float4*)&s_q[c][r][0];
        const float4 q1  = *(const float4*)&s_q[c][r][4];
        const float4 rq0 = *(const float4*)&s_rq[c][r][0];
        const float4 rq1 = *(const float4*)&s_rq[c][r][4];
        float dec[8];
        dec[0] = rintf(rintf(acc[0] * rq0.x) * q0.x);
        dec[1] = rintf(rintf(acc[1] * rq0.y) * q0.y);
        dec[2] = rintf(rintf(acc[2] * rq0.z) * q0.z);
        dec[3] = rintf(rintf(acc[3] * rq0.w) * q0.w);
        dec[4] = rintf(rintf(acc[4] * rq1.x) * q1.x);
        dec[5] = rintf(rintf(acc[5] * rq1.y) * q1.y);
        dec[6] = rintf(rintf(acc[6] * rq1.z) * q1.z);
        dec[7] = rintf(rintf(acc[7] * rq1.w) * q1.w);
        // V = dec * D  (row-local first IDCT stage)
        #pragma unroll
        for (int l = 0; l < 8; l++) V[l] = 0.0f;
        #pragma unroll
        for (int k = 0; k < 8; k++) {
            float t = dec[k];
            const float4 d0 = *(const float4*)&s_d[k][0];
            const float4 d1 = *(const float4*)&s_d[k][4];
            V[0] = fmaf(t, d0.x, V[0]);  V[1] = fmaf(t, d0.y, V[1]);
            V[2] = fmaf(t, d0.z, V[2]);  V[3] = fmaf(t, d0.w, V[3]);
            V[4] = fmaf(t, d1.x, V[4]);  V[5] = fmaf(t, d1.y, V[5]);
            V[6] = fmaf(t, d1.z, V[6]);  V[7] = fmaf(t, d1.w, V[7]);
        }
    }
    __syncthreads();  // all X reads done -> safe to overwrite s_a
    float* pW = &s_a[c][by*8][bx*8];
    *(float4*)(pW + r*SAW)     = make_float4(V[0], V[1], V[2], V[3]);
    *(float4*)(pW + r*SAW + 4) = make_float4(V[4], V[5], V[6], V[7]);
    __syncthreads();

    // ---- IDCT stage 2: Z = D^T * V ----
    float zr[8];
    {
        #pragma unroll
        for (int l = 0; l < 8; l++) zr[l] = 0.0f;
        #pragma unroll
        for (int j = 0; j < 8; j++) {
            float d = s_dt[r][j];
            const float4 v0 = *(const float4*)(pW + j*SAW);
            const float4 v1 = *(const float4*)(pW + j*SAW + 4);
            zr[0] = fmaf(d, v0.x, zr[0]);  zr[1] = fmaf(d, v0.y, zr[1]);
            zr[2] = fmaf(d, v0.z, zr[2]);  zr[3] = fmaf(d, v0.w, zr[3]);
            zr[4] = fmaf(d, v1.x, zr[4]);  zr[5] = fmaf(d, v1.y, zr[5]);
            zr[6] = fmaf(d, v1.z, zr[6]);  zr[7] = fmaf(d, v1.w, zr[7]);
        }
        const float off = (c == 0) ? 128.0f : 0.0f;
        #pragma unroll
        for (int l = 0; l < 8; l++) zr[l] += off;
    }
    __syncthreads();  // all V reads done -> safe to overwrite
    *(float4*)(pW + r*SAW)     = make_float4(zr[0], zr[1], zr[2], zr[3]);
    *(float4*)(pW + r*SAW + 4) = make_float4(zr[4], zr[5], zr[6], zr[7]);
    __syncthreads();

    // ---- phase 5: YCbCr -> RGB, clip, round, store ----
    if (tid < (TH * TW) / 4) {
        const int py  = tid >> 4;
        const int px4 = (tid & 15) * 4;
        const float4 yv  = *(const float4*)&s_a[0][py][px4];
        const float4 cbv = *(const float4*)&s_a[1][py][px4];
        const float4 crv = *(const float4*)&s_a[2][py][px4];

        #define FIN(v) (rintf(fminf(fmaxf((v), 0.0f), 255.0f)) * (1.0f/255.0f))
        float4 R, G, Bv;
        R.x = FIN(fmaf(1.402f, crv.x, yv.x));  R.y = FIN(fmaf(1.402f, crv.y, yv.y));
        R.z = FIN(fmaf(1.402f, crv.z, yv.z));  R.w = FIN(fmaf(1.402f, crv.w, yv.w));
        G.x = FIN(fmaf(-0.714136286f, crv.x, fmaf(-0.344136286f, cbv.x, yv.x)));
        G.y = FIN(fmaf(-0.714136286f, crv.y, fmaf(-0.344136286f, cbv.y, yv.y)));
        G.z = FIN(fmaf(-0.714136286f, crv.z, fmaf(-0.344136286f, cbv.z, yv.z)));
        G.w = FIN(fmaf(-0.714136286f, crv.w, fmaf(-0.344136286f, cbv.w, yv.w)));
        Bv.x = FIN(fmaf(1.772f, cbv.x, yv.x)); Bv.y = FIN(fmaf(1.772f, cbv.y, yv.y));
        Bv.z = FIN(fmaf(1.772f, cbv.z, yv.z)); Bv.w = FIN(fmaf(1.772f, cbv.w, yv.w));

        const size_t idx = (size_t)(ty0 + py) * WIMG + (tx0 + px4);
        *(float4*)&obase[idx]           = R;
        *(float4*)&obase[plane + idx]   = G;
        *(float4*)&obase[2*plane + idx] = Bv;
    }
}

extern "C" void kernel_launch(void* const* d_in, const int* in_sizes, int n_in,
                              void* d_out, int out_size)
{
    const float* x = nullptr;
    const float* q = nullptr;
    const float* d = nullptr;
    int nimg = 0;
    for (int i = 0; i < n_in; i++) {
        if (in_sizes[i] == 192)      q = (const float*)d_in[i];
        else if (in_sizes[i] == 64)  d = (const float*)d_in[i];
        else { x = (const float*)d_in[i]; nimg = in_sizes[i] / (3 * HIMG * WIMG); }
    }
    dim3 grid(WIMG / TW, HIMG / TH, nimg);
    jpeg_kernel<<<grid, NT>>>(x, q, d, (float*)d_out);
}